// round 4
// baseline (speedup 1.0000x reference)
#include <cuda_runtime.h>
#include <cuda_bf16.h>

// kspaceMap: out (32,129,128,128) f32.
//   channels 0..127: sep[b,w,h,w'] = (Re(t)cos(2pi w w'/128) - Im(t)sin(..))/128,
//                    t = row DFT_128 of input[:,0]. sep[128-w] == sep[w] (real input).
//   channel 128:     copy of input[b,1,h,:].  mask unused.
//
// R4: two kernels. A: per-(b,h) split-u DFT -> 2.1MB scratch [b][w][h] + ch128 copy.
//     B: per-(b,w) channel writer: contiguous 64KB slab stores (direct + mirror),
//        st.global.cs streaming hint, immediate-offset STG.128, packed f32x2 math.

#define IM  128
#define BZ  32
#define CH_OUT 129

typedef unsigned long long u64;

__device__ float2 g_t[BZ * 65 * IM];   // [b][w][h], t/128

static __device__ __forceinline__ u64 f2x(float a, float b) {
    u64 r; asm("mov.b64 %0, {%1, %2};" : "=l"(r) : "f"(a), "f"(b)); return r;
}
static __device__ __forceinline__ u64 mul2(u64 a, u64 b) {
    u64 d; asm("mul.rn.f32x2 %0, %1, %2;" : "=l"(d) : "l"(a), "l"(b)); return d;
}
static __device__ __forceinline__ u64 fma2(u64 a, u64 b, u64 c) {
    u64 d; asm("fma.rn.f32x2 %0, %1, %2, %3;" : "=l"(d) : "l"(a), "l"(b), "l"(c)); return d;
}
static __device__ __forceinline__ float2 unpk(u64 v) {
    float2 r; asm("mov.b64 {%0, %1}, %2;" : "=f"(r.x), "=f"(r.y) : "l"(v)); return r;
}

// ---- Phase A: DFT of each input row (b,h) -> g_t[b][0..64][h]; ch128 copy ----
__global__ void __launch_bounds__(IM) dft_kernel(const float* __restrict__ in,
                                                 float* __restrict__ out)
{
    const int bh  = blockIdx.x;
    const int b   = bh >> 7;
    const int h   = bh & (IM - 1);
    const int tid = threadIdx.x;

    __shared__ float  xs[IM];
    __shared__ float2 part[IM];

    const unsigned r0 = (((unsigned)b * 2 + 0) * IM + h) * IM;
    const unsigned r1 = (((unsigned)b * 2 + 1) * IM + h) * IM;
    xs[tid] = in[r0 + tid];
    __stcs(out + ((((unsigned)b * CH_OUT + IM) * IM + h) * IM + tid), in[r1 + tid]);
    __syncthreads();

    // thread = (bin w = tid&63, u-half = tid>>6), 64 MACs each, rotation twiddle
    {
        const int w    = tid & 63;
        const int half = tid >> 6;
        float S, C;  sincospif((float)w * (1.0f / 64.0f), &S, &C);  // step theta_w
        float s, c;  sincospif((float)(w * half), &s, &c);          // start u0 = 64*half (exact)
        float re = 0.0f, im = 0.0f;
        const float* xu = xs + (half << 6);
        #pragma unroll 8
        for (int u = 0; u < 64; ++u) {
            const float xv = xu[u];
            re = fmaf(xv,  c, re);
            im = fmaf(xv, -s, im);
            const float cn = fmaf(c, C, -(s * S));
            s = fmaf(s, C, c * S);
            c = cn;
        }
        part[tid] = make_float2(re, im);
    }
    // bin 64: t64 = sum x[u]*(-1)^u (real), warp 3 shuffle reduction
    if (tid >= 96) {
        const int l = tid & 31;
        float v = xs[l] + xs[l + 32] + xs[l + 64] + xs[l + 96];
        if (l & 1) v = -v;
        #pragma unroll
        for (int o = 16; o > 0; o >>= 1)
            v += __shfl_xor_sync(0xffffffffu, v, o);
        if (l == 0) g_t[((unsigned)b * 65 + 64) * IM + h] = make_float2(v * (1.0f / IM), 0.0f);
    }
    __syncthreads();
    if (tid < 64) {
        const float2 a = part[tid], d = part[tid + 64];
        g_t[((unsigned)b * 65 + tid) * IM + h] =
            make_float2((a.x + d.x) * (1.0f / IM), (a.y + d.y) * (1.0f / IM));
    }
}

// ---- Phase B: CTA (w,b) writes channel w (and mirror 128-w) contiguously ----
__global__ void __launch_bounds__(256) store_kernel(float* __restrict__ out)
{
    const int w   = blockIdx.x;          // 0..64
    const int b   = blockIdx.y;          // 0..31
    const int tid = threadIdx.x;
    const int lane = tid & 31;
    const int sub  = tid >> 5;           // 0..7

    __shared__ float2 st[IM];
    if (tid < IM) st[tid] = g_t[((unsigned)b * 65 + w) * IM + tid];

    // per-thread w' = 4*lane + k, fixed; twiddle angle*pi = (w*w')/64, reduced mod 128
    float c[4], s[4];
    #pragma unroll
    for (int k = 0; k < 4; ++k) {
        const int m = (w * (4 * lane + k)) & (IM - 1);
        sincospif((float)m * (1.0f / 64.0f), &s[k], &c[k]);
    }
    const u64 C01 = f2x(c[0], c[1]), S01 = f2x(s[0], s[1]);
    const u64 C23 = f2x(c[2], c[3]), S23 = f2x(s[2], s[3]);
    __syncthreads();

    float* p  = out + ((((unsigned)b * CH_OUT + w)        << 14) + (unsigned)tid * 4);
    float* pm = out + ((((unsigned)b * CH_OUT + (IM - w)) << 14) + (unsigned)tid * 4);
    const bool dm = (w >= 1) && (w <= 63);

    #pragma unroll
    for (int it = 0; it < 16; ++it) {
        const float2 tt = st[it * 8 + sub];        // LDS broadcast (warp-uniform)
        const u64 trx = f2x(tt.x, tt.x);
        const float nti = -tt.y;
        const u64 ntx = f2x(nti, nti);
        const u64 v01 = fma2(ntx, S01, mul2(trx, C01));
        const u64 v23 = fma2(ntx, S23, mul2(trx, C23));
        const float2 a = unpk(v01), d = unpk(v23);
        const float4 vv = make_float4(a.x, a.y, d.x, d.y);
        __stcs((float4*)(p + it * 1024), vv);
        if (dm) __stcs((float4*)(pm + it * 1024), vv);
    }
}

extern "C" void kernel_launch(void* const* d_in, const int* in_sizes, int n_in,
                              void* d_out, int out_size)
{
    const float* in  = (const float*)d_in[0];   // (32,2,128,128) f32
    float*       out = (float*)d_out;           // (32,129,128,128) f32
    (void)in_sizes; (void)n_in; (void)out_size;

    dft_kernel<<<BZ * IM, IM>>>(in, out);
    store_kernel<<<dim3(65, BZ), 256>>>(out);
}